// round 15
// baseline (speedup 1.0000x reference)
#include <cuda_runtime.h>

#define KK 16
#define LL 64
#define BB 32768
#define ROWF4 256          // 256 float4 per element row
#define NSUP (LL / 4)      // 16 super-chunks of 4 digits (256B per element/tensor)

__device__ __forceinline__ void cp16(unsigned dst, const float4* src) {
    asm volatile("cp.async.cg.shared.global [%0], [%1], 16;\n" :: "r"(dst), "l"(src));
}

// ROLE 0 = add (carry1 state), ROLE 1 = sub (borrow0 state, c reversed at unpack).
// Cyclic-16 conv via in-place CRT split (see R14).
template<int ROLE>
__device__ __forceinline__ void digit_math(
    const float4 Ain[4], const float4 Cin[4],
    float& t, float4* __restrict__ so)
{
    float a[16], c[16];
    #pragma unroll
    for (int w = 0; w < 4; ++w) {
        const float4 A = Ain[w], C = Cin[w];
        a[4*w+0] = A.x; a[4*w+1] = A.y; a[4*w+2] = A.z; a[4*w+3] = A.w;
        if (ROLE == 0) {
            c[4*w+0] = C.x; c[4*w+1] = C.y; c[4*w+2] = C.z; c[4*w+3] = C.w;
        } else {
            c[15-(4*w+0)] = C.x; c[15-(4*w+1)] = C.y;
            c[15-(4*w+2)] = C.z; c[15-(4*w+3)] = C.w;
        }
    }

    float S = 0.f;
    if (ROLE == 0) {
        float Cs[16];
        Cs[15] = c[15];
        #pragma unroll
        for (int m = 14; m >= 1; --m) Cs[m] = Cs[m + 1] + c[m];
        #pragma unroll
        for (int i = 1; i < 16; ++i) S = fmaf(a[i], Cs[16 - i], S);
    } else {
        float Cp[15];
        Cp[0] = c[0];
        #pragma unroll
        for (int m = 1; m < 15; ++m) Cp[m] = Cp[m - 1] + c[m];
        #pragma unroll
        for (int i = 0; i < 15; ++i) S = fmaf(a[i], Cp[14 - i], S);
    }

    #pragma unroll
    for (int i = 0; i < 8; ++i) {
        const float lo = a[i], hi = a[i + 8];
        a[i]     = lo + hi;
        a[i + 8] = lo - hi;
        const float th = 0.5f * c[i + 8];
        const float cl = c[i];
        c[i]     = fmaf(0.5f, cl,  th);
        c[i + 8] = fmaf(0.5f, cl, -th);
    }

    float Y[8], Z[8];
    #pragma unroll
    for (int v = 0; v < 8; ++v) { Y[v] = 0.f; Z[v] = 0.f; }
    #pragma unroll
    for (int i = 0; i < 8; ++i) {
        #pragma unroll
        for (int j = 0; j < 8; ++j) {
            Y[(i + j) & 7] = fmaf(a[i], c[j], Y[(i + j) & 7]);
            if (i + j < 8) Z[i + j]     = fmaf( a[8 + i], c[8 + j], Z[i + j]);
            else           Z[i + j - 8] = fmaf(-a[8 + i], c[8 + j], Z[i + j - 8]);
        }
    }

    #pragma unroll
    for (int v = 0; v < 8; ++v) {
        a[v]     = Y[v] + Z[v];
        a[v + 8] = Y[v] - Z[v];
    }

    float r[16];
    #pragma unroll
    for (int v = 0; v < 16; ++v)
        r[v] = fmaf(t, a[(v + 15) & 15] - a[v], a[v]);

    const float base = (ROLE == 0) ? S : (1.f - S - a[15]);
    t = fmaf(t, a[15], base);

    #pragma unroll
    for (int w = 0; w < 4; ++w)
        so[w] = make_float4(r[4*w], r[4*w+1], r[4*w+2], r[4*w+3]);
}

// Block = 64 threads: warp 0 = add, warp 1 = sub, 32 shared elements.
// Input staged in 256B spans per element row (4 digits), ring of 2 super-buffers.
__global__ __launch_bounds__(64) void bitop_kernel(
    const float4* __restrict__ op1, const float4* __restrict__ op2,
    float4* __restrict__ outa, float4* __restrict__ outs)
{
    __shared__ float4 sin[2][64][17];  // rows 0-31 op1, 32-63 op2; 16 slots + pad
    __shared__ float4 sou[2][32][9];   // per-warp output, one digit-pair

    const int tid = threadIdx.x;
    const int wid = tid >> 5;      // 0 = add, 1 = sub
    const int ln  = tid & 31;
    const int ebase = blockIdx.x * 32;

    // staging assignment: slot q16 of rows g4s+4r (r = 0..15)
    const int q16 = tid & 15;
    const int g4s = tid >> 4;      // 0..3

    unsigned sb[2];
    sb[0] = (unsigned)__cvta_generic_to_shared(&sin[0][0][0]);
    sb[1] = (unsigned)__cvta_generic_to_shared(&sin[1][0][0]);

    // one STAGE = full 256B span of every row (16 consecutive slots across lanes)
    #define STAGE(b, P)                                                       \
        do {                                                                  \
            _Pragma("unroll")                                                 \
            for (int r = 0; r < 16; ++r) {                                    \
                const int row = g4s + 4 * r;                                  \
                const float4* src = ((row < 32) ? op1 : op2)                  \
                    + (size_t)(ebase + (row & 31)) * ROWF4                    \
                    + (size_t)(P) * 16 + q16;                                 \
                cp16(sb[b] + row * 272 + q16 * 16, src);                      \
            }                                                                 \
            asm volatile("cp.async.commit_group;\n" ::);                      \
        } while (0)

    STAGE(0, 0);
    STAGE(1, 1);
    asm volatile("cp.async.wait_group 1;\n" ::);   // super 0 landed
    __syncthreads();

    float4 A1[4], C1[4], A2[4], C2[4];
    #pragma unroll
    for (int w = 0; w < 4; ++w) {
        A1[w] = sin[0][ln][w];
        C1[w] = sin[0][32 + ln][w];
    }

    const int q4 = ln & 7;
    const int g4 = ln >> 3;
    float4* const optr = wid ? outs : outa;
    const size_t obase[4] = {
        (size_t)(ebase + g4)      * ROWF4, (size_t)(ebase + g4 + 4)  * ROWF4,
        (size_t)(ebase + g4 + 8)  * ROWF4, (size_t)(ebase + g4 + 12) * ROWF4 };

    float t = wid ? 1.f : 0.f;

    #pragma unroll 1
    for (int P = 0; P < NSUP; ++P) {
        const int b = P & 1;

        // ---- pair 2P (digits 4P, 4P+1) ----
        #pragma unroll
        for (int w = 0; w < 4; ++w) {              // digit 4P+1
            A2[w] = sin[b][ln][4 + w];
            C2[w] = sin[b][32 + ln][4 + w];
        }
        if (wid == 0) digit_math<0>(A1, C1, t, &sou[0][ln][0]);
        else          digit_math<1>(A1, C1, t, &sou[1][ln][0]);

        #pragma unroll
        for (int w = 0; w < 4; ++w) {              // digit 4P+2
            A1[w] = sin[b][ln][8 + w];
            C1[w] = sin[b][32 + ln][8 + w];
        }
        if (wid == 0) digit_math<0>(A2, C2, t, &sou[0][ln][4]);
        else          digit_math<1>(A2, C2, t, &sou[1][ln][4]);
        __syncwarp();

        {   // stores pair 2P
            const size_t po = (size_t)(2 * P) * 8 + q4;
            #pragma unroll
            for (int r = 0; r < 4; ++r) {
                optr[obase[r] + po]                      = sou[wid][g4 + 4 * r][q4];
                optr[obase[r] + (size_t)16 * ROWF4 + po] = sou[wid][g4 + 4 * r + 16][q4];
            }
        }
        __syncwarp();

        // ---- pair 2P+1 (digits 4P+2, 4P+3) ----
        #pragma unroll
        for (int w = 0; w < 4; ++w) {              // digit 4P+3 (last sin[b] reads)
            A2[w] = sin[b][ln][12 + w];
            C2[w] = sin[b][32 + ln][12 + w];
        }
        if (wid == 0) digit_math<0>(A1, C1, t, &sou[0][ln][0]);
        else          digit_math<1>(A1, C1, t, &sou[1][ln][0]);

        __syncthreads();                           // all sin[b] reads complete
        if (P + 2 < NSUP) STAGE(b, P + 2);
        else asm volatile("cp.async.commit_group;\n" ::);   // keep group accounting

        if (P < NSUP - 1) {
            asm volatile("cp.async.wait_group 1;\n" ::);    // super P+1 landed
            __syncthreads();
            #pragma unroll
            for (int w = 0; w < 4; ++w) {          // digit 4(P+1)
                A1[w] = sin[b ^ 1][ln][w];
                C1[w] = sin[b ^ 1][32 + ln][w];
            }
        }

        if (wid == 0) digit_math<0>(A2, C2, t, &sou[0][ln][4]);
        else          digit_math<1>(A2, C2, t, &sou[1][ln][4]);
        __syncwarp();

        {   // stores pair 2P+1
            const size_t po = (size_t)(2 * P + 1) * 8 + q4;
            #pragma unroll
            for (int r = 0; r < 4; ++r) {
                optr[obase[r] + po]                      = sou[wid][g4 + 4 * r][q4];
                optr[obase[r] + (size_t)16 * ROWF4 + po] = sou[wid][g4 + 4 * r + 16][q4];
            }
        }
        __syncwarp();
    }
    #undef STAGE
}

extern "C" void kernel_launch(void* const* d_in, const int* in_sizes, int n_in,
                              void* d_out, int out_size)
{
    const float4* op1 = (const float4*)d_in[0];
    const float4* op2 = (const float4*)d_in[1];
    float* out = (float*)d_out;
    float4* outa = (float4*)out;
    float4* outs = (float4*)(out + (size_t)BB * LL * KK);

    bitop_kernel<<<BB / 32, 64>>>(op1, op2, outa, outs);
}

// round 16
// speedup vs baseline: 1.0118x; 1.0118x over previous
#include <cuda_runtime.h>

#define KK 16
#define LL 64
#define BB 32768
#define ROWF4 256          // 256 float4 per element row
#define NSUP (LL / 4)      // 16 super-chunks of 4 digits (256B per element/tensor)

__device__ __forceinline__ void cp16(unsigned dst, const float4* src) {
    asm volatile("cp.async.cg.shared.global [%0], [%1], 16;\n" :: "r"(dst), "l"(src));
}

// ROLE 0 = add (carry1 state), ROLE 1 = sub (borrow0 state, c reversed at unpack).
// Cyclic-16 conv via in-place CRT split (see R14).
template<int ROLE>
__device__ __forceinline__ void digit_math(
    const float4 Ain[4], const float4 Cin[4],
    float& t, float4* __restrict__ so)
{
    float a[16], c[16];
    #pragma unroll
    for (int w = 0; w < 4; ++w) {
        const float4 A = Ain[w], C = Cin[w];
        a[4*w+0] = A.x; a[4*w+1] = A.y; a[4*w+2] = A.z; a[4*w+3] = A.w;
        if (ROLE == 0) {
            c[4*w+0] = C.x; c[4*w+1] = C.y; c[4*w+2] = C.z; c[4*w+3] = C.w;
        } else {
            c[15-(4*w+0)] = C.x; c[15-(4*w+1)] = C.y;
            c[15-(4*w+2)] = C.z; c[15-(4*w+3)] = C.w;
        }
    }

    float S = 0.f;
    if (ROLE == 0) {
        float Cs[16];
        Cs[15] = c[15];
        #pragma unroll
        for (int m = 14; m >= 1; --m) Cs[m] = Cs[m + 1] + c[m];
        #pragma unroll
        for (int i = 1; i < 16; ++i) S = fmaf(a[i], Cs[16 - i], S);
    } else {
        float Cp[15];
        Cp[0] = c[0];
        #pragma unroll
        for (int m = 1; m < 15; ++m) Cp[m] = Cp[m - 1] + c[m];
        #pragma unroll
        for (int i = 0; i < 15; ++i) S = fmaf(a[i], Cp[14 - i], S);
    }

    #pragma unroll
    for (int i = 0; i < 8; ++i) {
        const float lo = a[i], hi = a[i + 8];
        a[i]     = lo + hi;
        a[i + 8] = lo - hi;
        const float th = 0.5f * c[i + 8];
        const float cl = c[i];
        c[i]     = fmaf(0.5f, cl,  th);
        c[i + 8] = fmaf(0.5f, cl, -th);
    }

    float Y[8], Z[8];
    #pragma unroll
    for (int v = 0; v < 8; ++v) { Y[v] = 0.f; Z[v] = 0.f; }
    #pragma unroll
    for (int i = 0; i < 8; ++i) {
        #pragma unroll
        for (int j = 0; j < 8; ++j) {
            Y[(i + j) & 7] = fmaf(a[i], c[j], Y[(i + j) & 7]);
            if (i + j < 8) Z[i + j]     = fmaf( a[8 + i], c[8 + j], Z[i + j]);
            else           Z[i + j - 8] = fmaf(-a[8 + i], c[8 + j], Z[i + j - 8]);
        }
    }

    #pragma unroll
    for (int v = 0; v < 8; ++v) {
        a[v]     = Y[v] + Z[v];
        a[v + 8] = Y[v] - Z[v];
    }

    float r[16];
    #pragma unroll
    for (int v = 0; v < 16; ++v)
        r[v] = fmaf(t, a[(v + 15) & 15] - a[v], a[v]);

    const float base = (ROLE == 0) ? S : (1.f - S - a[15]);
    t = fmaf(t, a[15], base);

    #pragma unroll
    for (int w = 0; w < 4; ++w)
        so[w] = make_float4(r[4*w], r[4*w+1], r[4*w+2], r[4*w+3]);
}

// Block = 64 threads: warp 0 = add, warp 1 = sub, 32 shared elements.
// Input staged in 256B spans per element row (4 digits), ring of 2 super-buffers.
__global__ __launch_bounds__(64) void bitop_kernel(
    const float4* __restrict__ op1, const float4* __restrict__ op2,
    float4* __restrict__ outa, float4* __restrict__ outs)
{
    __shared__ float4 sin[2][64][17];  // rows 0-31 op1, 32-63 op2; 16 slots + pad
    __shared__ float4 sou[2][32][9];   // per-warp output, one digit-pair

    const int tid = threadIdx.x;
    const int wid = tid >> 5;      // 0 = add, 1 = sub
    const int ln  = tid & 31;
    const int ebase = blockIdx.x * 32;

    // staging assignment: slot q16 of rows g4s+4r (r = 0..15)
    const int q16 = tid & 15;
    const int g4s = tid >> 4;      // 0..3

    unsigned sb[2];
    sb[0] = (unsigned)__cvta_generic_to_shared(&sin[0][0][0]);
    sb[1] = (unsigned)__cvta_generic_to_shared(&sin[1][0][0]);

    // one STAGE = full 256B span of every row (16 consecutive slots across lanes)
    #define STAGE(b, P)                                                       \
        do {                                                                  \
            _Pragma("unroll")                                                 \
            for (int r = 0; r < 16; ++r) {                                    \
                const int row = g4s + 4 * r;                                  \
                const float4* src = ((row < 32) ? op1 : op2)                  \
                    + (size_t)(ebase + (row & 31)) * ROWF4                    \
                    + (size_t)(P) * 16 + q16;                                 \
                cp16(sb[b] + row * 272 + q16 * 16, src);                      \
            }                                                                 \
            asm volatile("cp.async.commit_group;\n" ::);                      \
        } while (0)

    STAGE(0, 0);
    STAGE(1, 1);
    asm volatile("cp.async.wait_group 1;\n" ::);   // super 0 landed
    __syncthreads();

    float4 A1[4], C1[4], A2[4], C2[4];
    #pragma unroll
    for (int w = 0; w < 4; ++w) {
        A1[w] = sin[0][ln][w];
        C1[w] = sin[0][32 + ln][w];
    }

    const int q4 = ln & 7;
    const int g4 = ln >> 3;
    float4* const optr = wid ? outs : outa;
    const size_t obase[4] = {
        (size_t)(ebase + g4)      * ROWF4, (size_t)(ebase + g4 + 4)  * ROWF4,
        (size_t)(ebase + g4 + 8)  * ROWF4, (size_t)(ebase + g4 + 12) * ROWF4 };

    float t = wid ? 1.f : 0.f;

    #pragma unroll 1
    for (int P = 0; P < NSUP; ++P) {
        const int b = P & 1;

        // ---- pair 2P (digits 4P, 4P+1) ----
        #pragma unroll
        for (int w = 0; w < 4; ++w) {              // digit 4P+1
            A2[w] = sin[b][ln][4 + w];
            C2[w] = sin[b][32 + ln][4 + w];
        }
        if (wid == 0) digit_math<0>(A1, C1, t, &sou[0][ln][0]);
        else          digit_math<1>(A1, C1, t, &sou[1][ln][0]);

        #pragma unroll
        for (int w = 0; w < 4; ++w) {              // digit 4P+2
            A1[w] = sin[b][ln][8 + w];
            C1[w] = sin[b][32 + ln][8 + w];
        }
        if (wid == 0) digit_math<0>(A2, C2, t, &sou[0][ln][4]);
        else          digit_math<1>(A2, C2, t, &sou[1][ln][4]);
        __syncwarp();

        {   // stores pair 2P
            const size_t po = (size_t)(2 * P) * 8 + q4;
            #pragma unroll
            for (int r = 0; r < 4; ++r) {
                optr[obase[r] + po]                      = sou[wid][g4 + 4 * r][q4];
                optr[obase[r] + (size_t)16 * ROWF4 + po] = sou[wid][g4 + 4 * r + 16][q4];
            }
        }
        __syncwarp();

        // ---- pair 2P+1 (digits 4P+2, 4P+3) ----
        #pragma unroll
        for (int w = 0; w < 4; ++w) {              // digit 4P+3 (last sin[b] reads)
            A2[w] = sin[b][ln][12 + w];
            C2[w] = sin[b][32 + ln][12 + w];
        }
        if (wid == 0) digit_math<0>(A1, C1, t, &sou[0][ln][0]);
        else          digit_math<1>(A1, C1, t, &sou[1][ln][0]);

        __syncthreads();                           // all sin[b] reads complete
        if (P + 2 < NSUP) STAGE(b, P + 2);
        else asm volatile("cp.async.commit_group;\n" ::);   // keep group accounting

        if (P < NSUP - 1) {
            asm volatile("cp.async.wait_group 1;\n" ::);    // super P+1 landed
            __syncthreads();
            #pragma unroll
            for (int w = 0; w < 4; ++w) {          // digit 4(P+1)
                A1[w] = sin[b ^ 1][ln][w];
                C1[w] = sin[b ^ 1][32 + ln][w];
            }
        }

        if (wid == 0) digit_math<0>(A2, C2, t, &sou[0][ln][4]);
        else          digit_math<1>(A2, C2, t, &sou[1][ln][4]);
        __syncwarp();

        {   // stores pair 2P+1
            const size_t po = (size_t)(2 * P + 1) * 8 + q4;
            #pragma unroll
            for (int r = 0; r < 4; ++r) {
                optr[obase[r] + po]                      = sou[wid][g4 + 4 * r][q4];
                optr[obase[r] + (size_t)16 * ROWF4 + po] = sou[wid][g4 + 4 * r + 16][q4];
            }
        }
        __syncwarp();
    }
    #undef STAGE
}

extern "C" void kernel_launch(void* const* d_in, const int* in_sizes, int n_in,
                              void* d_out, int out_size)
{
    const float4* op1 = (const float4*)d_in[0];
    const float4* op2 = (const float4*)d_in[1];
    float* out = (float*)d_out;
    float4* outa = (float4*)out;
    float4* outs = (float4*)(out + (size_t)BB * LL * KK);

    bitop_kernel<<<BB / 32, 64>>>(op1, op2, outa, outs);
}